// round 2
// baseline (speedup 1.0000x reference)
#include <cuda_runtime.h>
#include <math.h>

#define DIM    64
#define NCODES 1024
#define NROWS  65536          // 16 * 64 * 64
#define HW     4096           // 64 * 64
#define QELEMS 4194304        // 16 * 64 * 64 * 64
#define FULL_OUT 71368706     // 1 + QELEMS + 1 + NROWS*NCODES + NROWS

// Scratch (no device mallocs allowed)
__device__ int    g_indices[NROWS];
__device__ float  g_b[NCODES];
__device__ int    g_hist[NCODES];
__device__ double g_loss;

// ---------------------------------------------------------------------------
// init: zero accumulators, compute b_k = ||e_k||^2 with reference-style
// rounding (round(mul) then round(add), sequential d order).
// ---------------------------------------------------------------------------
__global__ void init_kernel(const float* __restrict__ emb) {
    int t = threadIdx.x;                 // 1024 threads
    g_hist[t] = 0;
    if (t == 0) g_loss = 0.0;
    const float* e = emb + t * DIM;
    float s = 0.f;
#pragma unroll
    for (int d = 0; d < DIM; ++d) s = __fadd_rn(s, __fmul_rn(e[d], e[d]));
    g_b[t] = s;
}

// ---------------------------------------------------------------------------
// argmin: 128 rows/block, fp32 exact distances, per-row argmin with
// first-occurrence tie-break. Also accumulates histogram + loss sum.
// ---------------------------------------------------------------------------
__global__ __launch_bounds__(256) void argmin_kernel(
    const float* __restrict__ xin, const float* __restrict__ emb)
{
    __shared__ __align__(16) float Xs[DIM * 128];   // [d][row]  32 KB
    __shared__ __align__(16) float Es[64 * DIM];    // [code][d] 16 KB (reused as keys)

    int tid = threadIdx.x;
    int tr  = tid & 31;               // row group: rows tr*4 .. tr*4+3
    int tc  = tid >> 5;               // code group: codes tc*8 .. tc*8+7 per chunk
    int n0  = blockIdx.x * 128;
    int img = n0 >> 12;               // / 4096 (blocks never straddle images)
    int hw0 = n0 & 4095;
    const float* gbase = xin + (size_t)img * (DIM * HW) + hw0;

    // Stage X tile: NCHW -> smem[d][row], fully coalesced
    for (int i = tid; i < DIM * 128; i += 256) {
        int d = i >> 7;
        int r = i & 127;
        Xs[i] = gbase[d * HW + r];
    }
    __syncthreads();

    // a_r = ||x_row||^2, sequential d order, rounded mul + rounded add
    float a[4];
#pragma unroll
    for (int r = 0; r < 4; ++r) {
        int row = tr * 4 + r;
        float s = 0.f;
#pragma unroll
        for (int d = 0; d < DIM; ++d) {
            float v = Xs[d * 128 + row];
            s = __fadd_rn(s, __fmul_rn(v, v));
        }
        a[r] = s;
    }

    float best[4];
    int   bidx[4];
#pragma unroll
    for (int r = 0; r < 4; ++r) { best[r] = __int_as_float(0x7f800000); bidx[r] = 0; }

    for (int chunk = 0; chunk < 16; ++chunk) {
        __syncthreads();                         // prior-chunk Es reads done
        const float* ec = emb + chunk * (64 * DIM);
        for (int i = tid; i < 64 * DIM; i += 256) Es[i] = ec[i];
        __syncthreads();

        float acc[4][8];
#pragma unroll
        for (int r = 0; r < 4; ++r)
#pragma unroll
            for (int j = 0; j < 8; ++j) acc[r][j] = 0.f;

        // m = x . e  via sequential-d FMA chain (12x LDS.128 per 128 FMA)
#pragma unroll 4
        for (int dk = 0; dk < DIM; dk += 4) {
            float4 e4[8];
#pragma unroll
            for (int j = 0; j < 8; ++j)
                e4[j] = *(const float4*)&Es[(tc * 8 + j) * DIM + dk];
#pragma unroll
            for (int t = 0; t < 4; ++t) {
                float4 xv = *(const float4*)&Xs[(dk + t) * 128 + tr * 4];
#pragma unroll
                for (int j = 0; j < 8; ++j) {
                    float ev = ((const float*)&e4[j])[t];
                    acc[0][j] = __fmaf_rn(xv.x, ev, acc[0][j]);
                    acc[1][j] = __fmaf_rn(xv.y, ev, acc[1][j]);
                    acc[2][j] = __fmaf_rn(xv.z, ev, acc[2][j]);
                    acc[3][j] = __fmaf_rn(xv.w, ev, acc[3][j]);
                }
            }
        }

        // score with the reference's exact rounding chain:
        // d = round(round(a + b) - 2*m)      (2*m is exact)
#pragma unroll
        for (int j = 0; j < 8; ++j) {
            int code = chunk * 64 + tc * 8 + j;   // strictly ascending per thread
            float bb = g_b[code];
#pragma unroll
            for (int r = 0; r < 4; ++r) {
                float s = __fadd_rn(__fadd_rn(a[r], bb), -2.0f * acc[r][j]);
                if (s < best[r]) { best[r] = s; bidx[r] = code; }
            }
        }
    }

    // Cross-thread argmin: pack (score_bits << 32) | idx, atomicMin.
    // Scores are ~||x-e||^2 >> 0, so fp32 bits are order-preserving; on
    // equal scores the smaller index wins (== jnp.argmin first-occurrence).
    __syncthreads();
    unsigned long long* keys = (unsigned long long*)Es;   // reuse Es (16B aligned)
    if (tid < 128) keys[tid] = 0xFFFFFFFFFFFFFFFFull;
    __syncthreads();
#pragma unroll
    for (int r = 0; r < 4; ++r) {
        unsigned long long key =
            ((unsigned long long)__float_as_uint(best[r]) << 32) | (unsigned)bidx[r];
        atomicMin(&keys[tr * 4 + r], key);
    }
    __syncthreads();

    double lsum = 0.0;
    if (tid < 128) {
        int idx = (int)(keys[tid] & 0xFFFFFFFFull);
        g_indices[n0 + tid] = idx;
        atomicAdd(&g_hist[idx], 1);
        const float* e = emb + idx * DIM;
        float s = 0.f;
#pragma unroll
        for (int d = 0; d < DIM; ++d) {
            float dif = e[d] - Xs[d * 128 + tid];
            s = __fmaf_rn(dif, dif, s);
        }
        lsum = (double)s;
    }
#pragma unroll
    for (int off = 16; off; off >>= 1)
        lsum += __shfl_down_sync(0xffffffffu, lsum, off);
    if (tid < 128 && (tid & 31) == 0) atomicAdd(&g_loss, lsum);
}

// ---------------------------------------------------------------------------
// one-hot encodings (268 MB, the big write) + indices-as-float.
// Output base is only 8B-aligned (offset QELEMS+2 floats) -> float2 stores.
// ---------------------------------------------------------------------------
__global__ void encodings_kernel(float* __restrict__ oenc, float* __restrict__ oidx) {
    int n   = blockIdx.x;
    int idx = g_indices[n];
    int t   = threadIdx.x;                       // 256 threads, 2x float2 each
    float2* row = (float2*)(oenc + (size_t)n * NCODES);
#pragma unroll
    for (int k = 0; k < 2; ++k) {
        int j = t + k * 256;                     // float2 index 0..511, coalesced
        float2 z = make_float2(0.f, 0.f);
        if ((idx >> 1) == j) ((float*)&z)[idx & 1] = 1.0f;
        row[j] = z;
    }
    if (t == 0) oidx[n] = (float)idx;
}

// ---------------------------------------------------------------------------
// quantized_st in NCHW (value == embedding[idx], ST passthrough)
// ---------------------------------------------------------------------------
__global__ void quant_kernel(const float* __restrict__ emb, float* __restrict__ oq) {
    int o  = blockIdx.x * 256 + threadIdx.x;
    int w  = o & 63;
    int h  = (o >> 6) & 63;
    int c  = (o >> 12) & 63;
    int im = o >> 18;
    int n  = (im << 12) | (h << 6) | w;
    oq[o] = emb[g_indices[n] * DIM + c];
}

// ---------------------------------------------------------------------------
// finalize: loss scalar + perplexity from histogram
// ---------------------------------------------------------------------------
__global__ void finalize_kernel(float* __restrict__ oloss, float* __restrict__ operp) {
    int t = threadIdx.x;                         // 1024 threads
    double p = (double)g_hist[t] / 65536.0;
    double h = -p * log(p + 1e-10);
    __shared__ double sh[32];
#pragma unroll
    for (int off = 16; off; off >>= 1) h += __shfl_down_sync(0xffffffffu, h, off);
    if ((t & 31) == 0) sh[t >> 5] = h;
    __syncthreads();
    if (t < 32) {
        double v = sh[t];
#pragma unroll
        for (int off = 16; off; off >>= 1) v += __shfl_down_sync(0xffffffffu, v, off);
        if (t == 0) {
            operp[0] = (float)exp(v);
            oloss[0] = (float)(1.25 * (g_loss / (double)QELEMS));
        }
    }
}

// ---------------------------------------------------------------------------
extern "C" void kernel_launch(void* const* d_in, const int* in_sizes, int n_in,
                              void* d_out, int out_size) {
    const float* xin = (const float*)d_in[0];
    const float* emb = (const float*)d_in[1];
    // defensive: detect swapped input order via element counts
    if (n_in >= 2 && in_sizes[0] == NCODES * DIM && in_sizes[1] == QELEMS) {
        xin = (const float*)d_in[1];
        emb = (const float*)d_in[0];
    }
    float* out  = (float*)d_out;
    bool   full = (out_size >= FULL_OUT);
    float* o_q  = full ? out + 1 : out;          // fallback: quantized only

    init_kernel<<<1, 1024>>>(emb);
    argmin_kernel<<<512, 256>>>(xin, emb);
    quant_kernel<<<QELEMS / 256, 256>>>(emb, o_q);
    if (full) {
        encodings_kernel<<<NROWS, 256>>>(out + (size_t)QELEMS + 2,
                                         out + (size_t)QELEMS + 2 + (size_t)NROWS * NCODES);
        finalize_kernel<<<1, 1024>>>(out, out + QELEMS + 1);
    }
}